// round 1
// baseline (speedup 1.0000x reference)
#include <cuda_runtime.h>
#include <math.h>

#define NUM_M 2000000
#define NT 512
#define NGEN 120
#define NB1 1184

// ---- device scratch (no allocations allowed) ----
__device__ float g_w1T[256 * 32];
__device__ float g_w2T[128 * 256];
__device__ float g_w3T[512 * 128];
__device__ float g_R[NT * 256];
__device__ float g_part1[NB1 * 32];
__device__ float g_part2[NB1];
__device__ float g_svec[32];   // [0..15]=v_cur, [16..31]=v_tgt
__device__ float g_vfin[16];
__device__ float g_invS;
__device__ float g_logit_scratch[64 * NT]; // fallback if out buffer lacks logits space

// ---------------------------------------------------------------------------
// Transpose MLP weights for contiguous per-output access.
__global__ void k_prep(const float* __restrict__ w1, const float* __restrict__ w2,
                       const float* __restrict__ w3) {
    int idx = blockIdx.x * blockDim.x + threadIdx.x;
    if (idx < 256 * 32) { int o = idx >> 5, i = idx & 31; g_w1T[idx] = w1[i * 256 + o]; }
    if (idx < 128 * 256) { int o = idx >> 8, k = idx & 255; g_w2T[idx] = w2[k * 128 + o]; }
    if (idx < 512 * 128) { int o = idx >> 7, k = idx & 127; g_w3T[idx] = w3[k * 512 + o]; }
}

// ---------------------------------------------------------------------------
// Pass 1: v_cur[n] = sum_m v_src[m]*emb_hat[m,n]; v_tgt likewise. Deterministic
// two-stage reduction (per-block partials, fixed-order finalize).
__global__ void __launch_bounds__(256) k_pass1(const float* __restrict__ emb,
                                               const float* __restrict__ vs,
                                               const float* __restrict__ vt) {
    float ac[16], at[16];
#pragma unroll
    for (int n = 0; n < 16; n++) { ac[n] = 0.f; at[n] = 0.f; }
    int stride = gridDim.x * blockDim.x;
    for (int m = blockIdx.x * blockDim.x + threadIdx.x; m < NUM_M; m += stride) {
        const float4* row = (const float4*)(emb + (size_t)m * 16);
        float e[16];
        *(float4*)&e[0]  = row[0];
        *(float4*)&e[4]  = row[1];
        *(float4*)&e[8]  = row[2];
        *(float4*)&e[12] = row[3];
        float ss = 0.f;
#pragma unroll
        for (int n = 0; n < 16; n++) ss = fmaf(e[n], e[n], ss);
        float inv = rsqrtf(ss);
        float a = vs[m] * inv, b = vt[m] * inv;
#pragma unroll
        for (int n = 0; n < 16; n++) {
            ac[n] = fmaf(a, e[n], ac[n]);
            at[n] = fmaf(b, e[n], at[n]);
        }
    }
#pragma unroll
    for (int off = 16; off; off >>= 1) {
#pragma unroll
        for (int n = 0; n < 16; n++) {
            ac[n] += __shfl_xor_sync(0xFFFFFFFFu, ac[n], off);
            at[n] += __shfl_xor_sync(0xFFFFFFFFu, at[n], off);
        }
    }
    __shared__ float sw[8][32];
    int warp = threadIdx.x >> 5, lane = threadIdx.x & 31;
    if (lane == 0) {
#pragma unroll
        for (int n = 0; n < 16; n++) { sw[warp][n] = ac[n]; sw[warp][16 + n] = at[n]; }
    }
    __syncthreads();
    if (threadIdx.x < 32) {
        float s = 0.f;
#pragma unroll
        for (int w = 0; w < 8; w++) s += sw[w][threadIdx.x];
        g_part1[blockIdx.x * 32 + threadIdx.x] = s;
    }
}

__global__ void k_final1() {
    int tid = threadIdx.x;           // 256 threads
    int n = tid & 31, c = tid >> 5;  // 8 chunks
    float s = 0.f;
    for (int b = c; b < NB1; b += 8) s += g_part1[b * 32 + n];
    __shared__ float sh[256];
    sh[tid] = s;
    __syncthreads();
    if (tid < 32) {
        float t = 0.f;
#pragma unroll
        for (int cc = 0; cc < 8; cc++) t += sh[cc * 32 + tid];
        g_svec[tid] = t;
    }
}

// ---------------------------------------------------------------------------
// Precompute R_t = expm(sum_g tc[t,g]*bases[g]) for all 512 transitions.
// Scaling-and-squaring with order-10 Taylor (theta=0.25). One block per t,
// thread (i,j) owns one matrix entry.
__global__ void __launch_bounds__(256) k_expm(const float* __restrict__ tc,
                                              const float* __restrict__ bases) {
    int t = blockIdx.x;
    int tid = threadIdx.x;
    int i = tid >> 4, j = tid & 15;
    __shared__ float sc[NGEN];
    __shared__ float A[256], P[256];
    __shared__ float sred[256];
    if (tid < NGEN) sc[tid] = tc[t * NGEN + tid];
    __syncthreads();
    float om = 0.f;
    for (int g = 0; g < NGEN; g++) om = fmaf(sc[g], bases[g * 256 + tid], om);
    sred[tid] = om * om;
    __syncthreads();
    for (int off = 128; off; off >>= 1) {
        if (tid < off) sred[tid] += sred[tid + off];
        __syncthreads();
    }
    float fro = sqrtf(sred[0]);
    int s = 0;
    float f = fro;
    while (f > 0.25f && s < 30) { f *= 0.5f; s++; }
    float scale = ldexpf(1.0f, -s);
    A[tid] = om * scale;
    float diag = (i == j) ? 1.0f : 0.0f;
    __syncthreads();
    const int Q = 10;
    P[tid] = diag + A[tid] * (1.0f / Q);
    __syncthreads();
    for (int k = Q - 1; k >= 1; k--) {
        float m = 0.f;
#pragma unroll
        for (int kk = 0; kk < 16; kk++) m = fmaf(A[i * 16 + kk], P[kk * 16 + j], m);
        __syncthreads();
        P[tid] = diag + m * (1.0f / (float)k);
        __syncthreads();
    }
    for (int q = 0; q < s; q++) {
        float m = 0.f;
#pragma unroll
        for (int kk = 0; kk < 16; kk++) m = fmaf(P[i * 16 + kk], P[kk * 16 + j], m);
        __syncthreads();
        P[tid] = m;
        __syncthreads();
    }
    g_R[t * 256 + tid] = P[tid];
}

// ---------------------------------------------------------------------------
// Sequential 64-step scan: single block, 512 threads.
__global__ void __launch_bounds__(512) k_steps(const float* __restrict__ pb1,
                                               const float* __restrict__ pb2,
                                               const float* __restrict__ pb3,
                                               const float* __restrict__ gum,
                                               float* __restrict__ out_logits,
                                               int nsteps) {
    __shared__ float x[32];   // [0..15]=v, [16..31]=v_tgt (fixed)
    __shared__ float h1[256];
    __shared__ float h2[128];
    __shared__ float wv[16];
    __shared__ int wi[16];
    __shared__ int s_best;
    int tid = threadIdx.x;
    if (tid < 32) x[tid] = g_svec[tid];
    __syncthreads();

    for (int step = 0; step < nsteps; step++) {
        // --- h1 = relu(W1^T x + b1), 256 outputs, 32 MACs each ---
        if (tid < 256) {
            const float4* w = (const float4*)(g_w1T + tid * 32);
            float acc = 0.f;
#pragma unroll
            for (int c = 0; c < 8; c++) {
                float4 q = w[c];
                acc = fmaf(q.x, x[c * 4 + 0], acc);
                acc = fmaf(q.y, x[c * 4 + 1], acc);
                acc = fmaf(q.z, x[c * 4 + 2], acc);
                acc = fmaf(q.w, x[c * 4 + 3], acc);
            }
            h1[tid] = fmaxf(acc + pb1[tid], 0.0f);
        }
        __syncthreads();

        // --- h2 = relu(W2^T h1 + b2), 128 outputs, 4 threads/output ---
        {
            int o = tid >> 2, part = tid & 3;
            const float4* w = (const float4*)(g_w2T + o * 256 + part * 64);
            float acc = 0.f;
#pragma unroll
            for (int c = 0; c < 16; c++) {
                float4 q = w[c];
                int k = part * 64 + c * 4;
                acc = fmaf(q.x, h1[k + 0], acc);
                acc = fmaf(q.y, h1[k + 1], acc);
                acc = fmaf(q.z, h1[k + 2], acc);
                acc = fmaf(q.w, h1[k + 3], acc);
            }
            acc += __shfl_xor_sync(0xFFFFFFFFu, acc, 1);
            acc += __shfl_xor_sync(0xFFFFFFFFu, acc, 2);
            if (part == 0) h2[o] = fmaxf(acc + pb2[o], 0.0f);
        }
        __syncthreads();

        // --- logits = W3^T h2 + b3, 512 outputs, 128 MACs each ---
        float logit;
        {
            const float4* w = (const float4*)(g_w3T + tid * 128);
            float a0 = 0.f, a1 = 0.f, a2 = 0.f, a3 = 0.f;
#pragma unroll
            for (int c = 0; c < 32; c += 4) {
                float4 q0 = w[c], q1 = w[c + 1], q2 = w[c + 2], q3 = w[c + 3];
                int k = c * 4;
                a0 = fmaf(q0.x, h2[k + 0], a0);  a0 = fmaf(q0.y, h2[k + 1], a0);
                a0 = fmaf(q0.z, h2[k + 2], a0);  a0 = fmaf(q0.w, h2[k + 3], a0);
                a1 = fmaf(q1.x, h2[k + 4], a1);  a1 = fmaf(q1.y, h2[k + 5], a1);
                a1 = fmaf(q1.z, h2[k + 6], a1);  a1 = fmaf(q1.w, h2[k + 7], a1);
                a2 = fmaf(q2.x, h2[k + 8], a2);  a2 = fmaf(q2.y, h2[k + 9], a2);
                a2 = fmaf(q2.z, h2[k + 10], a2); a2 = fmaf(q2.w, h2[k + 11], a2);
                a3 = fmaf(q3.x, h2[k + 12], a3); a3 = fmaf(q3.y, h2[k + 13], a3);
                a3 = fmaf(q3.z, h2[k + 14], a3); a3 = fmaf(q3.w, h2[k + 15], a3);
            }
            logit = (a0 + a1) + (a2 + a3) + pb3[tid];
            out_logits[step * NT + tid] = logit;
        }

        // --- argmax of logits + gumbel (forward value of hard gumbel-softmax) ---
        float z = logit + gum[step * NT + tid];
        float bv = z;
        int bi = tid;
#pragma unroll
        for (int off = 16; off; off >>= 1) {
            float ov = __shfl_xor_sync(0xFFFFFFFFu, bv, off);
            int oi = __shfl_xor_sync(0xFFFFFFFFu, bi, off);
            if (ov > bv || (ov == bv && oi < bi)) { bv = ov; bi = oi; }
        }
        int warp = tid >> 5, lane = tid & 31;
        if (lane == 0) { wv[warp] = bv; wi[warp] = bi; }
        __syncthreads();
        if (tid == 0) {
            float best = wv[0];
            int besti = wi[0];
            for (int w = 1; w < 16; w++) {
                if (wv[w] > best || (wv[w] == best && wi[w] < besti)) { best = wv[w]; besti = wi[w]; }
            }
            s_best = besti;
        }
        __syncthreads();

        // --- v <- normalize(R[best] @ v), warp 0 ---
        if (tid < 32) {
            float nv = 0.f;
            if (tid < 16) {
                const float4* r = (const float4*)(g_R + s_best * 256 + tid * 16);
                float4 r0 = r[0], r1 = r[1], r2 = r[2], r3 = r[3];
                nv = r0.x * x[0]  + r0.y * x[1]  + r0.z * x[2]  + r0.w * x[3]
                   + r1.x * x[4]  + r1.y * x[5]  + r1.z * x[6]  + r1.w * x[7]
                   + r2.x * x[8]  + r2.y * x[9]  + r2.z * x[10] + r2.w * x[11]
                   + r3.x * x[12] + r3.y * x[13] + r3.z * x[14] + r3.w * x[15];
            }
            float sq = nv * nv;
#pragma unroll
            for (int off = 16; off; off >>= 1) sq += __shfl_xor_sync(0xFFFFFFFFu, sq, off);
            if (tid < 16) x[tid] = nv / sqrtf(sq);
        }
        __syncthreads();
    }
    if (tid < 16) g_vfin[tid] = x[tid];
}

// ---------------------------------------------------------------------------
// Pass 2: logits over memory, shifted softmax (logit <= 1 since both vectors
// are unit norm, so exp(logit-1) <= 1 — shift-invariant, no global max pass).
__global__ void __launch_bounds__(256) k_pass2(const float* __restrict__ emb,
                                               float* __restrict__ out) {
    __shared__ float sv[16];
    if (threadIdx.x < 16) sv[threadIdx.x] = g_vfin[threadIdx.x];
    __syncthreads();
    float vr[16];
#pragma unroll
    for (int n = 0; n < 16; n++) vr[n] = sv[n];
    float psum = 0.f;
    int stride = gridDim.x * blockDim.x;
    for (int m = blockIdx.x * blockDim.x + threadIdx.x; m < NUM_M; m += stride) {
        const float4* row = (const float4*)(emb + (size_t)m * 16);
        float e[16];
        *(float4*)&e[0]  = row[0];
        *(float4*)&e[4]  = row[1];
        *(float4*)&e[8]  = row[2];
        *(float4*)&e[12] = row[3];
        float ss = 0.f, dot = 0.f;
#pragma unroll
        for (int n = 0; n < 16; n++) { ss = fmaf(e[n], e[n], ss); dot = fmaf(vr[n], e[n], dot); }
        float ex = expf(dot * rsqrtf(ss) - 1.0f);
        out[m] = ex;
        psum += ex;
    }
#pragma unroll
    for (int off = 16; off; off >>= 1) psum += __shfl_xor_sync(0xFFFFFFFFu, psum, off);
    __shared__ float ws[8];
    int warp = threadIdx.x >> 5, lane = threadIdx.x & 31;
    if (lane == 0) ws[warp] = psum;
    __syncthreads();
    if (threadIdx.x == 0) {
        float s = 0.f;
#pragma unroll
        for (int w = 0; w < 8; w++) s += ws[w];
        g_part2[blockIdx.x] = s;
    }
}

__global__ void k_sum() {
    int tid = threadIdx.x;  // 1024 threads
    float s = 0.f;
    for (int b = tid; b < NB1; b += 1024) s += g_part2[b];
    __shared__ float sh[1024];
    sh[tid] = s;
    __syncthreads();
    for (int off = 512; off; off >>= 1) {
        if (tid < off) sh[tid] += sh[tid + off];
        __syncthreads();
    }
    if (tid == 0) g_invS = 1.0f / sh[0];
}

__global__ void __launch_bounds__(256) k_scale(float* __restrict__ out) {
    int i = blockIdx.x * blockDim.x + threadIdx.x;
    float inv = g_invS;
    if (i < NUM_M / 4) {
        float4* p = (float4*)out;
        float4 v = p[i];
        v.x *= inv; v.y *= inv; v.z *= inv; v.w *= inv;
        p[i] = v;
    }
}

// ---------------------------------------------------------------------------
extern "C" void kernel_launch(void* const* d_in, const int* in_sizes, int n_in,
                              void* d_out, int out_size) {
    const float* v_src = (const float*)d_in[0];
    const float* v_tgt = (const float*)d_in[1];
    const float* emb   = (const float*)d_in[2];
    const float* tc    = (const float*)d_in[3];
    const float* bases = (const float*)d_in[4];
    const float* b1    = (const float*)d_in[6];
    const float* b2    = (const float*)d_in[8];
    const float* b3    = (const float*)d_in[10];
    const float* gum   = (const float*)d_in[11];
    const float* w1    = (const float*)d_in[5];
    const float* w2    = (const float*)d_in[7];
    const float* w3    = (const float*)d_in[9];
    (void)bases; (void)n_in;

    int nsteps = in_sizes[11] / NT;  // gumbel is [nsteps, 1, 512]
    if (nsteps <= 0 || nsteps > 64) nsteps = 64;

    float* out = (float*)d_out;
    float* logits_dst;
    if (out_size >= NUM_M + nsteps * NT) {
        logits_dst = out + NUM_M;
    } else {
        // fall back to scratch (layout mismatch safety)
        cudaGetSymbolAddress((void**)&logits_dst, g_logit_scratch);
    }

    k_prep<<<256, 256>>>(w1, w2, w3);
    k_pass1<<<NB1, 256>>>(emb, v_src, v_tgt);
    k_final1<<<1, 256>>>();
    k_expm<<<NT, 256>>>(tc, (const float*)d_in[4]);
    k_steps<<<1, 512>>>(b1, b2, b3, gum, logits_dst, nsteps);
    k_pass2<<<NB1, 256>>>(emb, out);
    k_sum<<<1, 1024>>>();
    k_scale<<<(NUM_M / 4 + 255) / 256, 256>>>(out);
}

// round 2
// speedup vs baseline: 3.3271x; 3.3271x over previous
#include <cuda_runtime.h>
#include <math.h>

#define NUM_M 2000000
#define NT 512
#define NGEN 120
#define NB1 1184

#define P1_WARPS (NB1 * 8)          // 9472 warps
#define P1_STRIDE (P1_WARPS * 8)    // 75776 rows per sweep
#define P1_ITERS ((NUM_M + P1_STRIDE - 1) / P1_STRIDE)  // 27

// ---- device scratch (no allocations allowed) ----
__device__ float g_R[NT * 256];
__device__ float g_part1[NB1 * 32];
__device__ float g_part2[NB1];
__device__ __align__(16) float g_svec[32];   // [0..15]=v_cur, [16..31]=v_tgt
__device__ __align__(16) float g_vfin[16];
__device__ float g_invS;
__device__ float g_logit_scratch[64 * NT];

// ---------------------------------------------------------------------------
// Pass 1: v_cur[n] = sum_m v_src[m]*emb_hat[m,n]; v_tgt likewise.
// 4 lanes cooperate per row -> every warp load instruction is 512B contiguous.
__global__ void __launch_bounds__(256) k_pass1(const float* __restrict__ emb,
                                               const float* __restrict__ vs,
                                               const float* __restrict__ vt) {
    int tid = threadIdx.x;
    int lane = tid & 31;
    int sub = lane & 3;          // which float4 of the 16-float row
    int r = lane >> 2;           // row-in-warp (8 rows per warp iteration)
    int gwarp = (blockIdx.x * 256 + tid) >> 5;
    const float4* e4p = (const float4*)emb;

    float4 ac = make_float4(0.f, 0.f, 0.f, 0.f);
    float4 at = make_float4(0.f, 0.f, 0.f, 0.f);

    for (int it = 0; it < P1_ITERS; it++) {
        int row = gwarp * 8 + r + it * P1_STRIDE;
        bool ok = row < NUM_M;
        float4 e = ok ? e4p[(size_t)row * 4 + sub] : make_float4(0.f, 0.f, 0.f, 0.f);
        float ss = e.x * e.x + e.y * e.y + e.z * e.z + e.w * e.w;
        ss += __shfl_xor_sync(0xFFFFFFFFu, ss, 1);
        ss += __shfl_xor_sync(0xFFFFFFFFu, ss, 2);
        float inv = rsqrtf(ss);
        float a = ok ? vs[row] * inv : 0.f;
        float b = ok ? vt[row] * inv : 0.f;
        ac.x = fmaf(a, e.x, ac.x); ac.y = fmaf(a, e.y, ac.y);
        ac.z = fmaf(a, e.z, ac.z); ac.w = fmaf(a, e.w, ac.w);
        at.x = fmaf(b, e.x, at.x); at.y = fmaf(b, e.y, at.y);
        at.z = fmaf(b, e.z, at.z); at.w = fmaf(b, e.w, at.w);
    }
    // reduce across the 8 row-groups (lanes differing in bits 2..4)
#pragma unroll
    for (int off = 4; off <= 16; off <<= 1) {
        ac.x += __shfl_xor_sync(0xFFFFFFFFu, ac.x, off);
        ac.y += __shfl_xor_sync(0xFFFFFFFFu, ac.y, off);
        ac.z += __shfl_xor_sync(0xFFFFFFFFu, ac.z, off);
        ac.w += __shfl_xor_sync(0xFFFFFFFFu, ac.w, off);
        at.x += __shfl_xor_sync(0xFFFFFFFFu, at.x, off);
        at.y += __shfl_xor_sync(0xFFFFFFFFu, at.y, off);
        at.z += __shfl_xor_sync(0xFFFFFFFFu, at.z, off);
        at.w += __shfl_xor_sync(0xFFFFFFFFu, at.w, off);
    }
    __shared__ float sw[8][32];
    int warp = tid >> 5;
    if (lane < 4) {  // sub = lane, r = 0 rows; holds components lane*4..lane*4+3
        sw[warp][lane * 4 + 0] = ac.x; sw[warp][lane * 4 + 1] = ac.y;
        sw[warp][lane * 4 + 2] = ac.z; sw[warp][lane * 4 + 3] = ac.w;
        sw[warp][16 + lane * 4 + 0] = at.x; sw[warp][16 + lane * 4 + 1] = at.y;
        sw[warp][16 + lane * 4 + 2] = at.z; sw[warp][16 + lane * 4 + 3] = at.w;
    }
    __syncthreads();
    if (tid < 32) {
        float s = 0.f;
#pragma unroll
        for (int w = 0; w < 8; w++) s += sw[w][tid];
        g_part1[blockIdx.x * 32 + tid] = s;
    }
}

__global__ void k_final1() {
    int tid = threadIdx.x;           // 256 threads
    int n = tid & 31, c = tid >> 5;
    float s = 0.f;
    for (int b = c; b < NB1; b += 8) s += g_part1[b * 32 + n];
    __shared__ float sh[256];
    sh[tid] = s;
    __syncthreads();
    if (tid < 32) {
        float t = 0.f;
#pragma unroll
        for (int cc = 0; cc < 8; cc++) t += sh[cc * 32 + tid];
        g_svec[tid] = t;
    }
}

// ---------------------------------------------------------------------------
// expm of all 512 skew-symmetric generators. One WARP per transition.
// omega[i][j] (i<j) = -tc[t, kidx(i,j)] since each basis has a single +/-1 pair.
__device__ __forceinline__ int kidx(int a, int b) {
    return (a * (31 - a)) / 2 + (b - a - 1);
}

__global__ void __launch_bounds__(256) k_expm(const float* __restrict__ tc) {
    __shared__ float sP[8][256];
    __shared__ float stc[8][120];
    int warp = threadIdx.x >> 5, lane = threadIdx.x & 31;
    int t = blockIdx.x * 8 + warp;

    for (int g = lane; g < NGEN; g += 32) stc[warp][g] = tc[t * NGEN + g];
    __syncwarp();

    float s2 = 0.f;
    for (int g = lane; g < NGEN; g += 32) { float v = stc[warp][g]; s2 = fmaf(v, v, s2); }
#pragma unroll
    for (int off = 16; off; off >>= 1) s2 += __shfl_xor_sync(0xFFFFFFFFu, s2, off);
    float fro = sqrtf(2.0f * s2);
    int s = 0; float f = fro;
    while (f > 0.25f && s < 30) { f *= 0.5f; s++; }
    float sc = ldexpf(1.0f, -s);

    int i = lane >> 1, jb = (lane & 1) * 8;
    float Arow[16];  // full row i of scaled A (skew: reconstruct from tc)
#pragma unroll
    for (int k = 0; k < 16; k++) {
        float o;
        if (k > i)      o = -stc[warp][kidx(i, k)];
        else if (k < i) o =  stc[warp][kidx(k, i)];
        else            o = 0.f;
        Arow[k] = o * sc;
    }
    // init P = I + A/8 (this lane's 8 entries)
#pragma unroll
    for (int jj = 0; jj < 8; jj++) {
        int j = jb + jj;
        sP[warp][i * 16 + j] = ((i == j) ? 1.0f : 0.0f) + Arow[j] * 0.125f;
    }
    __syncwarp();

    // Horner Taylor, order 8
    for (int q = 7; q >= 1; q--) {
        float m[8];
#pragma unroll
        for (int jj = 0; jj < 8; jj++) {
            float acc = 0.f;
#pragma unroll
            for (int k = 0; k < 16; k++) acc = fmaf(Arow[k], sP[warp][k * 16 + jb + jj], acc);
            m[jj] = acc;
        }
        __syncwarp();
        float inv = 1.0f / (float)q;
#pragma unroll
        for (int jj = 0; jj < 8; jj++) {
            int j = jb + jj;
            sP[warp][i * 16 + j] = ((i == j) ? 1.0f : 0.0f) + m[jj] * inv;
        }
        __syncwarp();
    }
    // s squarings
    for (int q = 0; q < s; q++) {
        float Prow[16];
#pragma unroll
        for (int k = 0; k < 16; k++) Prow[k] = sP[warp][i * 16 + k];
        float m[8];
#pragma unroll
        for (int jj = 0; jj < 8; jj++) {
            float acc = 0.f;
#pragma unroll
            for (int k = 0; k < 16; k++) acc = fmaf(Prow[k], sP[warp][k * 16 + jb + jj], acc);
            m[jj] = acc;
        }
        __syncwarp();
#pragma unroll
        for (int jj = 0; jj < 8; jj++) sP[warp][i * 16 + jb + jj] = m[jj];
        __syncwarp();
    }
#pragma unroll
    for (int jj = 0; jj < 8; jj++)
        g_R[t * 256 + i * 16 + jb + jj] = sP[warp][i * 16 + jb + jj];
}

// ---------------------------------------------------------------------------
// Sequential 64-step scan: single block, 512 threads.
// smem: w1a(v half) 16KB + w2 128KB + w3[k<32] 64KB + state  (~221 KB)
#define S_W1A 0
#define S_W2  4096
#define S_W3  36864
#define S_B1P 53248
#define S_B2  53504
#define S_B3  53632
#define S_X   54144
#define S_H1  54160
#define S_H2  54416
#define S_PRT 54544
#define S_WV  56592
#define S_WI  56608
#define S_TOT 56624
#define STEPS_SMEM_BYTES (S_TOT * 4)

__global__ void __launch_bounds__(512) k_steps(const float* __restrict__ w1,
                                               const float* __restrict__ pb1,
                                               const float* __restrict__ w2,
                                               const float* __restrict__ pb2,
                                               const float* __restrict__ w3,
                                               const float* __restrict__ pb3,
                                               const float* __restrict__ gum,
                                               float* __restrict__ out_logits,
                                               int nsteps) {
    extern __shared__ float sm[];
    float* w1a = sm + S_W1A;   // [16][256]
    float* w2s = sm + S_W2;    // [256][128]
    float* w3s = sm + S_W3;    // [32][512]  (k = 0..31)
    float* b1p = sm + S_B1P;
    float* b2s = sm + S_B2;
    float* b3s = sm + S_B3;
    float* x   = sm + S_X;     // [16]
    float* h1  = sm + S_H1;    // [256]
    float* h2  = sm + S_H2;    // [128]
    float* prt = sm + S_PRT;   // [2048] shared scratch for both reductions
    float* wv  = sm + S_WV;
    int*   wi  = (int*)(sm + S_WI);

    int tid = threadIdx.x;

    // ---- prologue: stage weights ----
    {
        const float4* s1 = (const float4*)w1;
        float4* d1 = (float4*)w1a;
        for (int i = tid; i < 1024; i += 512) d1[i] = s1[i];       // w1 rows 0..15
        const float4* s2 = (const float4*)w2;
        float4* d2 = (float4*)w2s;
        for (int i = tid; i < 8192; i += 512) d2[i] = s2[i];
        const float4* s3 = (const float4*)w3;
        float4* d3 = (float4*)w3s;
        for (int i = tid; i < 4096; i += 512) d3[i] = s3[i];       // w3 k=0..31
        if (tid < 128) b2s[tid] = pb2[tid];
        b3s[tid] = pb3[tid];
        if (tid < 16) x[tid] = g_svec[tid];
        if (tid < 256) {
            float s = pb1[tid];
#pragma unroll
            for (int n = 0; n < 16; n++) s = fmaf(g_svec[16 + n], w1[(16 + n) * 256 + tid], s);
            b1p[tid] = s;
        }
    }
    __syncthreads();

    const float4* w2s4 = (const float4*)w2s;
    const float4* w3s4 = (const float4*)w3s;
    const float4* w3g4 = (const float4*)w3;
    float4* prt4 = (float4*)prt;

    for (int step = 0; step < nsteps; step++) {
        float gnoise = gum[step * NT + tid];  // prefetch early

        // --- h1 = relu(W1a^T v + b1'), 256 outputs ---
        if (tid < 256) {
            float acc = b1p[tid];
#pragma unroll
            for (int k = 0; k < 16; k++) acc = fmaf(x[k], w1a[k * 256 + tid], acc);
            h1[tid] = fmaxf(acc, 0.0f);
        }
        __syncthreads();

        // --- h2 = relu(W2^T h1 + b2): og owns 4 outputs, kk owns 16 k's ---
        {
            int og = tid & 31, kk = tid >> 5;      // og: float4 group, kk: 0..15
            int kb = kk * 16;
            float4 acc = make_float4(0.f, 0.f, 0.f, 0.f);
#pragma unroll
            for (int kc = 0; kc < 16; kc++) {
                int k = kb + kc;
                float4 w = w2s4[k * 32 + og];
                float hv = h1[k];
                acc.x = fmaf(hv, w.x, acc.x); acc.y = fmaf(hv, w.y, acc.y);
                acc.z = fmaf(hv, w.z, acc.z); acc.w = fmaf(hv, w.w, acc.w);
            }
            prt4[kk * 32 + og] = acc;
        }
        __syncthreads();
        if (tid < 128) {
            float s = b2s[tid];
#pragma unroll
            for (int kk = 0; kk < 16; kk++) s += prt[kk * 128 + tid];
            h2[tid] = fmaxf(s, 0.0f);
        }
        __syncthreads();

        // --- logits = W3^T h2 + b3: og owns 4 outputs (128 groups), kk: 0..3 ---
        {
            int og = tid & 127, kk = tid >> 7;
            float4 acc = make_float4(0.f, 0.f, 0.f, 0.f);
            if (kk == 0) {  // warp-uniform branch: k=0..31 from smem
#pragma unroll
                for (int kc = 0; kc < 32; kc++) {
                    float4 w = w3s4[kc * 128 + og];
                    float hv = h2[kc];
                    acc.x = fmaf(hv, w.x, acc.x); acc.y = fmaf(hv, w.y, acc.y);
                    acc.z = fmaf(hv, w.z, acc.z); acc.w = fmaf(hv, w.w, acc.w);
                }
            } else {        // k = 32kk..32kk+31 streamed from L2 (coalesced)
                int kb = kk * 32;
#pragma unroll
                for (int kc = 0; kc < 32; kc++) {
                    int k = kb + kc;
                    float4 w = w3g4[k * 128 + og];
                    float hv = h2[k];
                    acc.x = fmaf(hv, w.x, acc.x); acc.y = fmaf(hv, w.y, acc.y);
                    acc.z = fmaf(hv, w.z, acc.z); acc.w = fmaf(hv, w.w, acc.w);
                }
            }
            prt4[kk * 128 + og] = acc;
        }
        __syncthreads();

        // --- finalize logits, argmax(logit + gumbel) ---
        float logit = b3s[tid] + prt[tid] + prt[512 + tid] + prt[1024 + tid] + prt[1536 + tid];
        out_logits[step * NT + tid] = logit;
        float z = logit + gnoise;
        float bv = z;
        int bi = tid;
#pragma unroll
        for (int off = 16; off; off >>= 1) {
            float ov = __shfl_xor_sync(0xFFFFFFFFu, bv, off);
            int oi = __shfl_xor_sync(0xFFFFFFFFu, bi, off);
            if (ov > bv || (ov == bv && oi < bi)) { bv = ov; bi = oi; }
        }
        int warp = tid >> 5, lane = tid & 31;
        if (lane == 0) { wv[warp] = bv; wi[warp] = bi; }
        __syncthreads();

        // --- warp 0: pick winner, rotate, renormalize ---
        if (tid < 32) {
            int besti;
            if (tid == 0) {
                float best = wv[0]; besti = wi[0];
#pragma unroll
                for (int w = 1; w < 16; w++) {
                    if (wv[w] > best || (wv[w] == best && wi[w] < besti)) {
                        best = wv[w]; besti = wi[w];
                    }
                }
            }
            besti = __shfl_sync(0xFFFFFFFFu, besti, 0);
            float nv = 0.f;
            if (tid < 16) {
                const float4* rr = (const float4*)(g_R + besti * 256 + tid * 16);
                float4 r0 = rr[0], r1 = rr[1], r2 = rr[2], r3 = rr[3];
                nv = r0.x * x[0]  + r0.y * x[1]  + r0.z * x[2]  + r0.w * x[3]
                   + r1.x * x[4]  + r1.y * x[5]  + r1.z * x[6]  + r1.w * x[7]
                   + r2.x * x[8]  + r2.y * x[9]  + r2.z * x[10] + r2.w * x[11]
                   + r3.x * x[12] + r3.y * x[13] + r3.z * x[14] + r3.w * x[15];
            }
            float sq = nv * nv;
#pragma unroll
            for (int off = 16; off; off >>= 1) sq += __shfl_xor_sync(0xFFFFFFFFu, sq, off);
            if (tid < 16) x[tid] = nv / sqrtf(sq);
        }
        __syncthreads();
    }
    if (tid < 16) g_vfin[tid] = x[tid];
}

// ---------------------------------------------------------------------------
// Pass 2: shifted softmax over memory (logit <= 1: both vectors unit-norm).
__global__ void __launch_bounds__(256) k_pass2(const float* __restrict__ emb,
                                               float* __restrict__ out) {
    int tid = threadIdx.x;
    int lane = tid & 31;
    int sub = lane & 3, r = lane >> 2;
    int gwarp = (blockIdx.x * 256 + tid) >> 5;
    const float4* e4p = (const float4*)emb;
    float4 vr = ((const float4*)g_vfin)[sub];
    float psum = 0.f;

    for (int it = 0; it < P1_ITERS; it++) {
        int row = gwarp * 8 + r + it * P1_STRIDE;
        bool ok = row < NUM_M;
        float4 e = ok ? e4p[(size_t)row * 4 + sub] : make_float4(0.f, 0.f, 0.f, 0.f);
        float ss = e.x * e.x + e.y * e.y + e.z * e.z + e.w * e.w;
        float dt = vr.x * e.x + vr.y * e.y + vr.z * e.z + vr.w * e.w;
        ss += __shfl_xor_sync(0xFFFFFFFFu, ss, 1);
        ss += __shfl_xor_sync(0xFFFFFFFFu, ss, 2);
        dt += __shfl_xor_sync(0xFFFFFFFFu, dt, 1);
        dt += __shfl_xor_sync(0xFFFFFFFFu, dt, 2);
        if (ok && sub == 0) {
            float ex = __expf(fmaf(dt, rsqrtf(ss), -1.0f));
            out[row] = ex;
            psum += ex;
        }
    }
#pragma unroll
    for (int off = 16; off; off >>= 1) psum += __shfl_xor_sync(0xFFFFFFFFu, psum, off);
    __shared__ float ws[8];
    int warp = tid >> 5;
    if (lane == 0) ws[warp] = psum;
    __syncthreads();
    if (tid == 0) {
        float s = 0.f;
#pragma unroll
        for (int w = 0; w < 8; w++) s += ws[w];
        g_part2[blockIdx.x] = s;
    }
}

__global__ void k_sum() {
    int tid = threadIdx.x;  // 1024 threads
    float s = 0.f;
    for (int b = tid; b < NB1; b += 1024) s += g_part2[b];
    __shared__ float sh[1024];
    sh[tid] = s;
    __syncthreads();
    for (int off = 512; off; off >>= 1) {
        if (tid < off) sh[tid] += sh[tid + off];
        __syncthreads();
    }
    if (tid == 0) g_invS = 1.0f / sh[0];
}

__global__ void __launch_bounds__(256) k_scale(float* __restrict__ out) {
    int i = blockIdx.x * blockDim.x + threadIdx.x;
    float inv = g_invS;
    if (i < NUM_M / 4) {
        float4* p = (float4*)out;
        float4 v = p[i];
        v.x *= inv; v.y *= inv; v.z *= inv; v.w *= inv;
        p[i] = v;
    }
}

// ---------------------------------------------------------------------------
extern "C" void kernel_launch(void* const* d_in, const int* in_sizes, int n_in,
                              void* d_out, int out_size) {
    const float* v_src = (const float*)d_in[0];
    const float* v_tgt = (const float*)d_in[1];
    const float* emb   = (const float*)d_in[2];
    const float* tc    = (const float*)d_in[3];
    const float* w1    = (const float*)d_in[5];
    const float* b1    = (const float*)d_in[6];
    const float* w2    = (const float*)d_in[7];
    const float* b2    = (const float*)d_in[8];
    const float* w3    = (const float*)d_in[9];
    const float* b3    = (const float*)d_in[10];
    const float* gum   = (const float*)d_in[11];
    (void)n_in;

    int nsteps = in_sizes[11] / NT;
    if (nsteps <= 0 || nsteps > 64) nsteps = 64;

    float* out = (float*)d_out;
    float* logits_dst;
    if (out_size >= NUM_M + nsteps * NT) {
        logits_dst = out + NUM_M;
    } else {
        cudaGetSymbolAddress((void**)&logits_dst, g_logit_scratch);
    }

    static int attr_done = 0;
    if (!attr_done) {
        cudaFuncSetAttribute(k_steps, cudaFuncAttributeMaxDynamicSharedMemorySize,
                             STEPS_SMEM_BYTES);
        attr_done = 1;
    }

    k_pass1<<<NB1, 256>>>(emb, v_src, v_tgt);
    k_final1<<<1, 256>>>();
    k_expm<<<NT / 8, 256>>>(tc);
    k_steps<<<1, 512, STEPS_SMEM_BYTES>>>(w1, b1, w2, b2, w3, b3, gum, logits_dst, nsteps);
    k_pass2<<<NB1, 256>>>(emb, out);
    k_sum<<<1, 1024>>>();
    k_scale<<<(NUM_M / 4 + 255) / 256, 256>>>(out);
}

// round 5
// speedup vs baseline: 3.8950x; 1.1707x over previous
#include <cuda_runtime.h>
#include <math.h>
#include <stdint.h>

#define NUM_M 2000000
#define NT 512
#define NGEN 120
#define NB1 1184

#define P1_WARPS (NB1 * 8)            // 9472 warps
#define P1_STRIDE2 (P1_WARPS * 16)    // 151552 rows per sweep (16 rows/warp)
#define P1_ITERS2 ((NUM_M + P1_STRIDE2 - 1) / P1_STRIDE2)  // 14

// ---- device scratch (no allocations allowed) ----
__device__ float g_R[NT * 256];
__device__ float g_part1[NB1 * 32];
__device__ float g_part2[NB1];
__device__ __align__(16) float g_svec[32];   // [0..15]=v_cur, [16..31]=v_tgt
__device__ __align__(16) float g_vfin[16];
__device__ float g_invS;
__device__ float g_logit_scratch[64 * NT];

// ===========================================================================
// PTX helpers for cluster DSMEM + mbarrier
// ===========================================================================
__device__ __forceinline__ uint32_t smem_u32(const void* p) {
    uint32_t a;
    asm("{ .reg .u64 t; cvta.to.shared.u64 t, %1; cvt.u32.u64 %0, t; }"
        : "=r"(a) : "l"(p));
    return a;
}
__device__ __forceinline__ uint32_t cl_rank() {
    uint32_t r; asm("mov.u32 %0, %%cluster_ctarank;" : "=r"(r)); return r;
}
__device__ __forceinline__ uint32_t mapa_u32(uint32_t a, uint32_t r) {
    uint32_t o;
    asm("mapa.shared::cluster.u32 %0, %1, %2;" : "=r"(o) : "r"(a), "r"(r));
    return o;
}
__device__ __forceinline__ void mbar_init(uint32_t a, uint32_t cnt) {
    asm volatile("mbarrier.init.shared.b64 [%0], %1;" :: "r"(a), "r"(cnt) : "memory");
}
__device__ __forceinline__ void mbar_arrive_cl(uint32_t a) {
    asm volatile("mbarrier.arrive.release.cluster.shared::cluster.b64 _, [%0];"
                 :: "r"(a) : "memory");
}
__device__ __forceinline__ void mbar_wait_cl(uint32_t a, uint32_t parity) {
    asm volatile(
        "{\n\t.reg .pred P;\n"
        "W%=:\n\t"
        "mbarrier.try_wait.parity.acquire.cluster.shared::cta.b64 P, [%0], %1, 0x989680;\n\t"
        "@P bra D%=;\n\t"
        "bra W%=;\n"
        "D%=:\n\t}"
        :: "r"(a), "r"(parity) : "memory");
}
__device__ __forceinline__ void st_cl_f32(uint32_t a, float v) {
    asm volatile("st.shared::cluster.f32 [%0], %1;" :: "r"(a), "f"(v) : "memory");
}
__device__ __forceinline__ void st_cl_u32(uint32_t a, uint32_t v) {
    asm volatile("st.shared::cluster.u32 [%0], %1;" :: "r"(a), "r"(v) : "memory");
}
__device__ __forceinline__ void cluster_sync_hw() {
    asm volatile("barrier.cluster.arrive.aligned;" ::: "memory");
    asm volatile("barrier.cluster.wait.aligned;" ::: "memory");
}

// ---------------------------------------------------------------------------
// Pass 1: v_cur[n] = sum_m v_src[m]*emb_hat[m,n]; v_tgt likewise.
// NOTE: rsqrtf argument clamped — OOB rows have ss=0 and rsqrtf(0)=inf would
// make 0*inf=NaN poison the accumulators (the R3/R4 bug).
__global__ void __launch_bounds__(256) k_pass1(const float* __restrict__ emb,
                                               const float* __restrict__ vs,
                                               const float* __restrict__ vt) {
    int tid = threadIdx.x;
    int lane = tid & 31;
    int sub = lane & 3;
    int r = lane >> 2;
    int gwarp = (blockIdx.x * 256 + tid) >> 5;
    const float4* e4p = (const float4*)emb;
    const float4 zf4 = make_float4(0.f, 0.f, 0.f, 0.f);

    float4 ac = zf4, at = zf4;

    for (int it = 0; it < P1_ITERS2; it++) {
        int base = gwarp * 16 + it * P1_STRIDE2;
        int row0 = base + r, row1 = base + 8 + r;
        bool ok0 = row0 < NUM_M, ok1 = row1 < NUM_M;
        float4 e0 = ok0 ? e4p[(size_t)row0 * 4 + sub] : zf4;
        float4 e1 = ok1 ? e4p[(size_t)row1 * 4 + sub] : zf4;
        float s0 = ok0 ? vs[row0] : 0.f;
        float t0 = ok0 ? vt[row0] : 0.f;
        float s1 = ok1 ? vs[row1] : 0.f;
        float t1 = ok1 ? vt[row1] : 0.f;
        float ss0 = e0.x * e0.x + e0.y * e0.y + e0.z * e0.z + e0.w * e0.w;
        float ss1 = e1.x * e1.x + e1.y * e1.y + e1.z * e1.z + e1.w * e1.w;
        ss0 += __shfl_xor_sync(0xFFFFFFFFu, ss0, 1);
        ss1 += __shfl_xor_sync(0xFFFFFFFFu, ss1, 1);
        ss0 += __shfl_xor_sync(0xFFFFFFFFu, ss0, 2);
        ss1 += __shfl_xor_sync(0xFFFFFFFFu, ss1, 2);
        float i0 = rsqrtf(fmaxf(ss0, 1e-35f));   // finite even for OOB rows
        float i1 = rsqrtf(fmaxf(ss1, 1e-35f));
        float a0 = s0 * i0, b0 = t0 * i0;
        float a1 = s1 * i1, b1 = t1 * i1;
        ac.x = fmaf(a0, e0.x, ac.x); ac.y = fmaf(a0, e0.y, ac.y);
        ac.z = fmaf(a0, e0.z, ac.z); ac.w = fmaf(a0, e0.w, ac.w);
        at.x = fmaf(b0, e0.x, at.x); at.y = fmaf(b0, e0.y, at.y);
        at.z = fmaf(b0, e0.z, at.z); at.w = fmaf(b0, e0.w, at.w);
        ac.x = fmaf(a1, e1.x, ac.x); ac.y = fmaf(a1, e1.y, ac.y);
        ac.z = fmaf(a1, e1.z, ac.z); ac.w = fmaf(a1, e1.w, ac.w);
        at.x = fmaf(b1, e1.x, at.x); at.y = fmaf(b1, e1.y, at.y);
        at.z = fmaf(b1, e1.z, at.z); at.w = fmaf(b1, e1.w, at.w);
    }
#pragma unroll
    for (int off = 4; off <= 16; off <<= 1) {
        ac.x += __shfl_xor_sync(0xFFFFFFFFu, ac.x, off);
        ac.y += __shfl_xor_sync(0xFFFFFFFFu, ac.y, off);
        ac.z += __shfl_xor_sync(0xFFFFFFFFu, ac.z, off);
        ac.w += __shfl_xor_sync(0xFFFFFFFFu, ac.w, off);
        at.x += __shfl_xor_sync(0xFFFFFFFFu, at.x, off);
        at.y += __shfl_xor_sync(0xFFFFFFFFu, at.y, off);
        at.z += __shfl_xor_sync(0xFFFFFFFFu, at.z, off);
        at.w += __shfl_xor_sync(0xFFFFFFFFu, at.w, off);
    }
    __shared__ float sw[8][32];
    int warp = tid >> 5;
    if (lane < 4) {
        sw[warp][lane * 4 + 0] = ac.x; sw[warp][lane * 4 + 1] = ac.y;
        sw[warp][lane * 4 + 2] = ac.z; sw[warp][lane * 4 + 3] = ac.w;
        sw[warp][16 + lane * 4 + 0] = at.x; sw[warp][16 + lane * 4 + 1] = at.y;
        sw[warp][16 + lane * 4 + 2] = at.z; sw[warp][16 + lane * 4 + 3] = at.w;
    }
    __syncthreads();
    if (tid < 32) {
        float s = 0.f;
#pragma unroll
        for (int w = 0; w < 8; w++) s += sw[w][tid];
        g_part1[blockIdx.x * 32 + tid] = s;
    }
}

__global__ void k_final1() {
    int tid = threadIdx.x;
    int n = tid & 31, c = tid >> 5;
    float s = 0.f;
    for (int b = c; b < NB1; b += 8) s += g_part1[b * 32 + n];
    __shared__ float sh[256];
    sh[tid] = s;
    __syncthreads();
    if (tid < 32) {
        float t = 0.f;
#pragma unroll
        for (int cc = 0; cc < 8; cc++) t += sh[cc * 32 + tid];
        g_svec[tid] = t;
    }
}

// ---------------------------------------------------------------------------
// expm of all 512 skew-symmetric generators. One warp per transition.
__device__ __forceinline__ int kidx(int a, int b) {
    return (a * (31 - a)) / 2 + (b - a - 1);
}

__global__ void __launch_bounds__(256) k_expm(const float* __restrict__ tc) {
    __shared__ float sP[8][256];
    __shared__ float stc[8][120];
    int warp = threadIdx.x >> 5, lane = threadIdx.x & 31;
    int t = blockIdx.x * 8 + warp;

    for (int g = lane; g < NGEN; g += 32) stc[warp][g] = tc[t * NGEN + g];
    __syncwarp();

    float s2 = 0.f;
    for (int g = lane; g < NGEN; g += 32) { float v = stc[warp][g]; s2 = fmaf(v, v, s2); }
#pragma unroll
    for (int off = 16; off; off >>= 1) s2 += __shfl_xor_sync(0xFFFFFFFFu, s2, off);
    float fro = sqrtf(2.0f * s2);
    int s = 0; float f = fro;
    while (f > 0.25f && s < 30) { f *= 0.5f; s++; }
    float sc = ldexpf(1.0f, -s);

    int i = lane >> 1, jb = (lane & 1) * 8;
    float Arow[16];
#pragma unroll
    for (int k = 0; k < 16; k++) {
        float o;
        if (k > i)      o = -stc[warp][kidx(i, k)];
        else if (k < i) o =  stc[warp][kidx(k, i)];
        else            o = 0.f;
        Arow[k] = o * sc;
    }
#pragma unroll
    for (int jj = 0; jj < 8; jj++) {
        int j = jb + jj;
        sP[warp][i * 16 + j] = ((i == j) ? 1.0f : 0.0f) + Arow[j] * 0.125f;
    }
    __syncwarp();

    for (int q = 7; q >= 1; q--) {
        float m[8];
#pragma unroll
        for (int jj = 0; jj < 8; jj++) {
            float acc = 0.f;
#pragma unroll
            for (int k = 0; k < 16; k++) acc = fmaf(Arow[k], sP[warp][k * 16 + jb + jj], acc);
            m[jj] = acc;
        }
        __syncwarp();
        float inv = 1.0f / (float)q;
#pragma unroll
        for (int jj = 0; jj < 8; jj++) {
            int j = jb + jj;
            sP[warp][i * 16 + j] = ((i == j) ? 1.0f : 0.0f) + m[jj] * inv;
        }
        __syncwarp();
    }
    for (int q = 0; q < s; q++) {
        float Prow[16];
#pragma unroll
        for (int k = 0; k < 16; k++) Prow[k] = sP[warp][i * 16 + k];
        float m[8];
#pragma unroll
        for (int jj = 0; jj < 8; jj++) {
            float acc = 0.f;
#pragma unroll
            for (int k = 0; k < 16; k++) acc = fmaf(Prow[k], sP[warp][k * 16 + jb + jj], acc);
            m[jj] = acc;
        }
        __syncwarp();
#pragma unroll
        for (int jj = 0; jj < 8; jj++) sP[warp][i * 16 + jb + jj] = m[jj];
        __syncwarp();
    }
#pragma unroll
    for (int jj = 0; jj < 8; jj++)
        g_R[t * 256 + i * 16 + jb + jj] = sP[warp][i * 16 + jb + jj];
}

// ---------------------------------------------------------------------------
// Sequential 64-step scan: 4-CTA cluster, each CTA owns 1/4 of w2 and w3.
#define S_W1A  0        // [16][256]                 4096
#define S_W2   4096     // [256][32] slice            8192
#define S_W3   12288    // [128][128] slice          16384
#define S_B1P  28672    // 256
#define S_B2   28928    // 32
#define S_B3   28960    // 128
#define S_X    29088    // 16
#define S_H1   29104    // 256
#define S_H2   29360    // 128 (full, assembled)
#define S_PRT  29488    // 2048
#define S_WV   31536    // 4
#define S_WI   31540    // 4
#define S_CV   31544    // 4
#define S_CI   31548    // 4
#define S_MBAR 31552    // 2 x uint64 (8B aligned)
#define S_TOT  31560
#define STEPS_SMEM_BYTES (S_TOT * 4)
#define CLSZ 4

__global__ void __launch_bounds__(512, 1) __cluster_dims__(CLSZ, 1, 1)
k_steps(const float* __restrict__ w1,  const float* __restrict__ pb1,
        const float* __restrict__ w2,  const float* __restrict__ pb2,
        const float* __restrict__ w3,  const float* __restrict__ pb3,
        const float* __restrict__ gum, float* __restrict__ out_logits,
        int nsteps) {
    extern __shared__ float sm[];
    float* w1a = sm + S_W1A;
    float* b1p = sm + S_B1P;
    float* b2s = sm + S_B2;
    float* b3s = sm + S_B3;
    float* x   = sm + S_X;
    float* h1  = sm + S_H1;
    float* h2  = sm + S_H2;
    float* prt = sm + S_PRT;
    float* wv  = sm + S_WV;
    int*   wi  = (int*)(sm + S_WI);
    float* cv  = sm + S_CV;
    int*   ci  = (int*)(sm + S_CI);
    float4* w2s4 = (float4*)(sm + S_W2);
    float4* w3s4 = (float4*)(sm + S_W3);
    float4* prt4 = (float4*)prt;

    int tid = threadIdx.x;
    uint32_t rank = cl_rank();
    uint32_t bar1 = smem_u32(sm + S_MBAR);
    uint32_t bar2 = bar1 + 8;

    // ---- prologue: stage slices; zero all exchange buffers ----
    {
        const float4* s1 = (const float4*)w1;
        float4* d1 = (float4*)w1a;
        for (int i = tid; i < 1024; i += 512) d1[i] = s1[i];
        const float4* w2g4 = (const float4*)w2;   // row stride 32 float4
        for (int i = tid; i < 2048; i += 512) {
            int k = i >> 3, og = i & 7;
            w2s4[i] = w2g4[k * 32 + rank * 8 + og];
        }
        const float4* w3g4 = (const float4*)w3;   // row stride 128 float4
        for (int i = tid; i < 4096; i += 512) {
            int k = i >> 5, og = i & 31;
            w3s4[i] = w3g4[k * 128 + rank * 32 + og];
        }
        if (tid < 32) b2s[tid] = pb2[rank * 32 + tid];
        if (tid < 128) b3s[tid] = pb3[rank * 128 + tid];
        if (tid < 16) x[tid] = g_svec[tid];
        if (tid < 128) h2[tid] = 0.f;               // defined bits everywhere
        if (tid < 4)  { cv[tid] = 0.f; ci[tid] = 0; }
        for (int i = tid; i < 2048; i += 512) prt[i] = 0.f;
        if (tid >= 256) {
            int o = tid - 256;
            float s = pb1[o];
#pragma unroll
            for (int n = 0; n < 16; n++) s = fmaf(g_svec[16 + n], w1[(16 + n) * 256 + o], s);
            b1p[o] = s;
        }
        // bar1: 32 writer lanes x 4 CTAs each arrive (per-lane release ordering).
        // bar2: 1 writer thread x 4 CTAs.
        if (tid == 0) { mbar_init(bar1, 32 * CLSZ); mbar_init(bar2, CLSZ); }
    }
    __syncthreads();
    cluster_sync_hw();   // peers' mbarriers + slices visible before remote traffic

    // precomputed remote addresses for the 32 h2-writer threads
    uint32_t h2rem[CLSZ];   // h2 slot in each rank (incl. self)
    uint32_t b1rem[CLSZ];   // bar1 in each rank
    if (tid < 32) {
        uint32_t loc = smem_u32(&h2[rank * 32 + tid]);
#pragma unroll
        for (uint32_t r = 0; r < CLSZ; r++) {
            h2rem[r] = mapa_u32(loc, r);
            b1rem[r] = mapa_u32(bar1, r);
        }
    }

    for (int step = 0; step < nsteps; step++) {
        uint32_t par = (uint32_t)(step & 1);
        float gn = 0.f;
        if (tid < 128) gn = gum[step * NT + rank * 128 + tid];

        // --- L1: full h1 in every CTA ---
        if (tid < 256) {
            float acc = b1p[tid];
#pragma unroll
            for (int k = 0; k < 16; k++) acc = fmaf(x[k], w1a[k * 256 + tid], acc);
            h1[tid] = fmaxf(acc, 0.0f);
        }
        __syncthreads();

        // --- L2 slice: 32 outputs; tid<128: og=tid&7, kk=tid>>3 (16 k's each) ---
        if (tid < 128) {
            int og = tid & 7, kk = tid >> 3, kb = kk * 16;
            float4 acc = make_float4(0.f, 0.f, 0.f, 0.f);
#pragma unroll
            for (int i = 0; i < 16; i++) {
                int k = kb + i;
                float4 w = w2s4[k * 8 + og];
                float hv = h1[k];
                acc.x = fmaf(hv, w.x, acc.x); acc.y = fmaf(hv, w.y, acc.y);
                acc.z = fmaf(hv, w.z, acc.z); acc.w = fmaf(hv, w.w, acc.w);
            }
            prt4[kk * 8 + og] = acc;
        }
        __syncthreads();
        if (tid < 32) {
            float s = b2s[tid];
#pragma unroll
            for (int kk = 0; kk < 16; kk++) s += prt[kk * 32 + tid];
            s = fmaxf(s, 0.0f);
            // broadcast own h2 value to all 4 CTAs (incl. self), then THIS lane
            // arrives with release on all 4 barriers -> its stores are ordered.
#pragma unroll
            for (uint32_t r = 0; r < CLSZ; r++) st_cl_f32(h2rem[r], s);
#pragma unroll
            for (uint32_t r = 0; r < CLSZ; r++) mbar_arrive_cl(b1rem[r]);
        }
        mbar_wait_cl(bar1, par);

        // --- L3 slice: 128 outputs; og=tid&31, kk=tid>>5 (8 k's each) ---
        {
            int og = tid & 31, kk = tid >> 5, kb = kk * 8;
            float4 acc = make_float4(0.f, 0.f, 0.f, 0.f);
#pragma unroll
            for (int i = 0; i < 8; i++) {
                int k = kb + i;
                float4 w = w3s4[k * 32 + og];
                float hv = h2[k];
                acc.x = fmaf(hv, w.x, acc.x); acc.y = fmaf(hv, w.y, acc.y);
                acc.z = fmaf(hv, w.z, acc.z); acc.w = fmaf(hv, w.w, acc.w);
            }
            prt4[kk * 32 + og] = acc;
        }
        __syncthreads();

        // --- finalize 128 logits, local argmax ---
        if (tid < 128) {
            float logit = b3s[tid];
#pragma unroll
            for (int kk = 0; kk < 16; kk++) logit += prt[kk * 128 + tid];
            out_logits[step * NT + rank * 128 + tid] = logit;
            float z = logit + gn;
            float bv = z;
            int bi = (int)(rank * 128) + tid;
#pragma unroll
            for (int off = 16; off; off >>= 1) {
                float ov = __shfl_xor_sync(0xFFFFFFFFu, bv, off);
                int oi = __shfl_xor_sync(0xFFFFFFFFu, bi, off);
                if (ov > bv || (ov == bv && oi < bi)) { bv = ov; bi = oi; }
            }
            if ((tid & 31) == 0) { wv[tid >> 5] = bv; wi[tid >> 5] = bi; }
        }
        __syncthreads();
        if (tid < 32) {
            float bv = (tid < 4) ? wv[tid] : -1e30f;
            int bi = (tid < 4) ? wi[tid] : 0x7FFFFFFF;
#pragma unroll
            for (int off = 1; off <= 2; off <<= 1) {
                float ov = __shfl_xor_sync(0xFFFFFFFFu, bv, off);
                int oi = __shfl_xor_sync(0xFFFFFFFFu, bi, off);
                if (ov > bv || (ov == bv && oi < bi)) { bv = ov; bi = oi; }
            }
            if (tid == 0) {
                uint32_t cvloc = smem_u32(&cv[rank]);
                uint32_t ciloc = smem_u32(&ci[rank]);
#pragma unroll
                for (uint32_t r = 0; r < CLSZ; r++) {
                    st_cl_f32(mapa_u32(cvloc, r), bv);
                    st_cl_u32(mapa_u32(ciloc, r), (uint32_t)bi);
                }
                // storing thread == arriving thread: release covers both stores
#pragma unroll
                for (uint32_t r = 0; r < CLSZ; r++) mbar_arrive_cl(mapa_u32(bar2, r));
            }
        }
        mbar_wait_cl(bar2, par);

        // --- winner + rotate + renormalize (replicated, warp 0) ---
        if (tid < 32) {
            float best = cv[0];
            int besti = ci[0];
#pragma unroll
            for (int r = 1; r < CLSZ; r++) {
                float ov = cv[r]; int oi = ci[r];
                if (ov > best || (ov == best && oi < besti)) { best = ov; besti = oi; }
            }
            float nv = 0.f;
            if (tid < 16) {
                const float4* rr = (const float4*)(g_R + besti * 256 + tid * 16);
                float4 r0 = __ldg(rr + 0), r1 = __ldg(rr + 1);
                float4 r2 = __ldg(rr + 2), r3 = __ldg(rr + 3);
                nv = r0.x * x[0]  + r0.y * x[1]  + r0.z * x[2]  + r0.w * x[3]
                   + r1.x * x[4]  + r1.y * x[5]  + r1.z * x[6]  + r1.w * x[7]
                   + r2.x * x[8]  + r2.y * x[9]  + r2.z * x[10] + r2.w * x[11]
                   + r3.x * x[12] + r3.y * x[13] + r3.z * x[14] + r3.w * x[15];
            }
            float sq = nv * nv;
#pragma unroll
            for (int off = 8; off; off >>= 1) sq += __shfl_xor_sync(0xFFFFFFFFu, sq, off);
            if (tid < 16) x[tid] = nv / sqrtf(sq);
        }
        __syncthreads();
    }
    if (rank == 0 && tid < 16) g_vfin[tid] = x[tid];
    cluster_sync_hw();  // no CTA exits while peers may still touch its smem
}

// ---------------------------------------------------------------------------
// Pass 2: shifted softmax over memory (logit <= 1: both vectors unit-norm).
__global__ void __launch_bounds__(256) k_pass2(const float* __restrict__ emb,
                                               float* __restrict__ out) {
    int tid = threadIdx.x;
    int lane = tid & 31;
    int sub = lane & 3, r = lane >> 2;
    int gwarp = (blockIdx.x * 256 + tid) >> 5;
    const float4* e4p = (const float4*)emb;
    const float4 zf4 = make_float4(0.f, 0.f, 0.f, 0.f);
    float4 vr = ((const float4*)g_vfin)[sub];
    float psum = 0.f;

    for (int it = 0; it < P1_ITERS2; it++) {
        int base = gwarp * 16 + it * P1_STRIDE2;
        int row0 = base + r, row1 = base + 8 + r;
        bool ok0 = row0 < NUM_M, ok1 = row1 < NUM_M;
        float4 e0 = ok0 ? e4p[(size_t)row0 * 4 + sub] : zf4;
        float4 e1 = ok1 ? e4p[(size_t)row1 * 4 + sub] : zf4;
        float ss0 = e0.x * e0.x + e0.y * e0.y + e0.z * e0.z + e0.w * e0.w;
        float ss1 = e1.x * e1.x + e1.y * e1.y + e1.z * e1.z + e1.w * e1.w;
        float d0 = vr.x * e0.x + vr.y * e0.y + vr.z * e0.z + vr.w * e0.w;
        float d1 = vr.x * e1.x + vr.y * e1.y + vr.z * e1.z + vr.w * e1.w;
        ss0 += __shfl_xor_sync(0xFFFFFFFFu, ss0, 1);
        ss1 += __shfl_xor_sync(0xFFFFFFFFu, ss1, 1);
        d0  += __shfl_xor_sync(0xFFFFFFFFu, d0, 1);
        d1  += __shfl_xor_sync(0xFFFFFFFFu, d1, 1);
        ss0 += __shfl_xor_sync(0xFFFFFFFFu, ss0, 2);
        ss1 += __shfl_xor_sync(0xFFFFFFFFu, ss1, 2);
        d0  += __shfl_xor_sync(0xFFFFFFFFu, d0, 2);
        d1  += __shfl_xor_sync(0xFFFFFFFFu, d1, 2);
        if (sub == 0) {
            if (ok0) {
                float ex = __expf(fmaf(d0, rsqrtf(ss0), -1.0f));
                out[row0] = ex;
                psum += ex;
            }
            if (ok1) {
                float ex = __expf(fmaf(d1, rsqrtf(ss1), -1.0f));
                out[row1] = ex;
                psum += ex;
            }
        }
    }
#pragma unroll
    for (int off = 16; off; off >>= 1) psum += __shfl_xor_sync(0xFFFFFFFFu, psum, off);
    __shared__ float ws[8];
    int warp = tid >> 5;
    if (lane == 0) ws[warp] = psum;
    __syncthreads();
    if (tid == 0) {
        float s = 0.f;
#pragma unroll
        for (int w = 0; w < 8; w++) s += ws[w];
        g_part2[blockIdx.x] = s;
    }
}

__global__ void k_sum() {
    int tid = threadIdx.x;
    float s = 0.f;
    for (int b = tid; b < NB1; b += 1024) s += g_part2[b];
    __shared__ float sh[1024];
    sh[tid] = s;
    __syncthreads();
    for (int off = 512; off; off >>= 1) {
        if (tid < off) sh[tid] += sh[tid + off];
        __syncthreads();
    }
    if (tid == 0) g_invS = 1.0f / sh[0];
}

__global__ void __launch_bounds__(256) k_scale(float* __restrict__ out) {
    int i = blockIdx.x * blockDim.x + threadIdx.x;
    float inv = g_invS;
    if (i < NUM_M / 4) {
        float4* p = (float4*)out;
        float4 v = p[i];
        v.x *= inv; v.y *= inv; v.z *= inv; v.w *= inv;
        p[i] = v;
    }
}

// ---------------------------------------------------------------------------
extern "C" void kernel_launch(void* const* d_in, const int* in_sizes, int n_in,
                              void* d_out, int out_size) {
    const float* v_src = (const float*)d_in[0];
    const float* v_tgt = (const float*)d_in[1];
    const float* emb   = (const float*)d_in[2];
    const float* tc    = (const float*)d_in[3];
    const float* w1    = (const float*)d_in[5];
    const float* b1    = (const float*)d_in[6];
    const float* w2    = (const float*)d_in[7];
    const float* b2    = (const float*)d_in[8];
    const float* w3    = (const float*)d_in[9];
    const float* b3    = (const float*)d_in[10];
    const float* gum   = (const float*)d_in[11];
    (void)n_in;

    int nsteps = in_sizes[11] / NT;
    if (nsteps <= 0 || nsteps > 64) nsteps = 64;

    float* out = (float*)d_out;
    float* logits_dst;
    if (out_size >= NUM_M + nsteps * NT) {
        logits_dst = out + NUM_M;
    } else {
        cudaGetSymbolAddress((void**)&logits_dst, g_logit_scratch);
    }

    cudaFuncSetAttribute(k_steps, cudaFuncAttributeMaxDynamicSharedMemorySize,
                         STEPS_SMEM_BYTES);

    k_pass1<<<NB1, 256>>>(emb, v_src, v_tgt);
    k_final1<<<1, 256>>>();
    k_expm<<<NT / 8, 256>>>(tc);
    k_steps<<<CLSZ, 512, STEPS_SMEM_BYTES>>>(w1, b1, w2, b2, w3, b3, gum,
                                             logits_dst, nsteps);
    k_pass2<<<NB1, 256>>>(emb, out);
    k_sum<<<1, 1024>>>();
    k_scale<<<(NUM_M / 4 + 255) / 256, 256>>>(out);
}